// round 15
// baseline (speedup 1.0000x reference)
#include <cuda_runtime.h>
#include <cuda_fp16.h>
#include <cstdint>

// ---------------------------------------------------------------------------
// DoubleAttention, restructured (A-conv algebraically eliminated), all-fp16
// operands resident in GMEM (one-time cvt pre-pass; GEMM epilogues emit fp16
// intermediates directly):
//   xh, wBh, wVh, wAh = fp16(x, wB, wV, wA)
//   L16 = [wBh;wVh] xh + bias    (2x GEMM M=512, N=4096, K=512 -> fp16 logits)
//   Bm, av = softmax_rows(L16)   (fp16 in/out, f32 math)
//   Sp  = Bm @ xh^T              (split-K=4, f32 partials) ; S16 = reduce(Sp)
//   gdT = wAh @ S16^T + bA       (fp16 out, O(1) values)
//   out = (gdT @ av) * 1/HW      (f32 out; 1/HW folded at the end)
// GEMM: m16n8k16 fp16 mma, f32 accum, BK=32 (2 k-slices/tile: compute-per-sync
// ~2x the L2 latency), double buffer, compile-time buffer indices.
// SMEM = half2 k-pair-major, stride 136, swizzle col^(((kp>>2)&3)<<3):
// fragment loads and all store paths bank-conflict-free (proof in round notes).
// ---------------------------------------------------------------------------

#define BB   8
#define CC   512
#define HW_  4096

#define BM 128
#define BN 128
#define BK 32          // two m16n8k16 slices per tile
#define KP 16          // BK/2 half2 k-pair rows
#define PAD 8          // row stride 136 words = 8 mod 32

#define NSPLIT4 4

// Scratch (__device__ globals; allocation is forbidden)
__device__ __half g_xh[BB * CC * HW_];                 // 33.5MB
__device__ __half g_wh[3 * CC * CC];                   // wB | wV | wA, 1.5MB
__device__ __half g_logits16[BB * 2 * CC * HW_];       // 67MB
__device__ float  g_Sp[NSPLIT4 * BB * CC * CC];        // 33.5MB split-K partials
__device__ __half g_S16[BB * CC * CC];                 // 4MB
__device__ __half g_gd16[BB * CC * CC];                // 4MB (holds gd^T)

// pack2(e,o): low half = e
__device__ __forceinline__ uint32_t pack2(float e, float o) {
    uint32_t u;
    asm("cvt.rn.f16x2.f32 %0, %1, %2;" : "=r"(u) : "f"(o), "f"(e));
    return u;
}
__device__ __forceinline__ uint32_t prmt(uint32_t a, uint32_t b, uint32_t s) {
    uint32_t d;
    asm("prmt.b32 %0, %1, %2, %3;" : "=r"(d) : "r"(a), "r"(b), "r"(s));
    return d;
}
__device__ __forceinline__ void mma16(float* c, const uint32_t* a, const uint32_t* b) {
    asm volatile(
        "mma.sync.aligned.m16n8k16.row.col.f32.f16.f16.f32 "
        "{%0,%1,%2,%3},{%4,%5,%6,%7},{%8,%9},{%0,%1,%2,%3};"
        : "+f"(c[0]), "+f"(c[1]), "+f"(c[2]), "+f"(c[3])
        : "r"(a[0]), "r"(a[1]), "r"(a[2]), "r"(a[3]), "r"(b[0]), "r"(b[1]));
}

// D[m,n] = scale * sum_k A[m,k]*B'[n,k]  (+ biasScale*bias[row or col])
// A ALWAYS [M,K] row-major fp16. TB: B [N,K] row-major; else [K,N].
// OUT16: D is fp16; else f32. NSPLIT: split-K partial at D + sp*sSplit.
template <bool TB, int NSPLIT, bool OUT16>
__global__ __launch_bounds__(128, 2) void gemm_h(
    const __half* __restrict__ Abase, const __half* __restrict__ Bbase,
    void* __restrict__ Dbase, int N, int K,
    long sA, long sB, long sD, long sSplit,
    const float* __restrict__ bias, int biasMode, float scale, float biasScale)
{
    __shared__ uint32_t As[2][KP][BM + PAD];   // 17.4KB
    __shared__ uint32_t Bs[2][KP][BN + PAD];   // 17.4KB

    const int bz    = blockIdx.z;
    const int batch = bz / NSPLIT;
    const int sp    = bz % NSPLIT;
    const int Kl    = K / NSPLIT;
    const int koff  = sp * Kl;

    const __half* A  = Abase + (long)batch * sA;
    const __half* Bp = Bbase + (long)batch * sB;

    const int bm   = blockIdx.y * BM;
    const int bn   = blockIdx.x * BN;
    const int tid  = threadIdx.x;
    const int lane = tid & 31;
    const int warp = tid >> 5;
    const int m0   = (warp >> 1) * 64;  // 2 warps along M
    const int n0   = (warp & 1) * 64;   // 2 warps along N
    const int r    = lane >> 2;         // 0..7
    const int cg   = lane & 3;          // 0..3

    float acc[4][8][4];
#pragma unroll
    for (int i = 0; i < 4; i++)
#pragma unroll
        for (int j = 0; j < 8; j++)
#pragma unroll
            for (int k = 0; k < 4; k++) acc[i][j][k] = 0.f;

    uint4 pa[4], pb[4];

    auto loadA = [&](int k0) {   // A [M,K] fp16: 128x32 halfs = 512 x 16B
#pragma unroll
        for (int i = 0; i < 4; i++) {
            int idx = tid + i * 128;
            int m = idx >> 2, kq = idx & 3;   // kq: which 8-k octet
            pa[i] = *reinterpret_cast<const uint4*>(&A[(long)(bm + m) * K + k0 + kq * 8]);
        }
    };
    auto storeA = [&](uint32_t (*Asb)[BM + PAD]) {
#pragma unroll
        for (int i = 0; i < 4; i++) {
            int idx = tid + i * 128;
            int m = idx >> 2, kq = idx & 3;
            int cs = m ^ (kq << 3);   // swz(m, kp) with kp>>2 == kq
            Asb[kq * 4 + 0][cs] = pa[i].x;
            Asb[kq * 4 + 1][cs] = pa[i].y;
            Asb[kq * 4 + 2][cs] = pa[i].z;
            Asb[kq * 4 + 3][cs] = pa[i].w;
        }
    };
    auto loadB = [&](int k0) {
        if (!TB) {   // B [K,N]: pair rows k=2kp, 2kp+1; 16 kp x 16 n-octets
#pragma unroll
            for (int i = 0; i < 2; i++) {
                int idx = tid + i * 128;
                int n8 = idx & 15, kp = idx >> 4;
                const __half* q = Bp + (long)(k0 + 2 * kp) * N + bn + n8 * 8;
                pb[2 * i]     = *reinterpret_cast<const uint4*>(q);
                pb[2 * i + 1] = *reinterpret_cast<const uint4*>(q + N);
            }
        } else {     // B [N,K] row-major
#pragma unroll
            for (int i = 0; i < 4; i++) {
                int idx = tid + i * 128;
                int n = idx >> 2, kq = idx & 3;
                pb[i] = *reinterpret_cast<const uint4*>(&Bp[(long)(bn + n) * K + k0 + kq * 8]);
            }
        }
    };
    auto storeB = [&](uint32_t (*Bsb)[BN + PAD]) {
        if (!TB) {   // interleave k-pairs with prmt, 2x STS.128 per unit
#pragma unroll
            for (int i = 0; i < 2; i++) {
                int idx = tid + i * 128;
                int n8 = idx & 15, kp = idx >> 4;
                uint4 a = pb[2 * i], b = pb[2 * i + 1];
                int col0 = (n8 * 8) ^ (((kp >> 2) & 3) << 3);
                uint4 w0 = make_uint4(prmt(a.x, b.x, 0x5410), prmt(a.x, b.x, 0x7632),
                                      prmt(a.y, b.y, 0x5410), prmt(a.y, b.y, 0x7632));
                uint4 w1 = make_uint4(prmt(a.z, b.z, 0x5410), prmt(a.z, b.z, 0x7632),
                                      prmt(a.w, b.w, 0x5410), prmt(a.w, b.w, 0x7632));
                *reinterpret_cast<uint4*>(&Bsb[kp][col0])     = w0;
                *reinterpret_cast<uint4*>(&Bsb[kp][col0 + 4]) = w1;
            }
        } else {     // transpose path, conflict-free (same proof as storeA)
#pragma unroll
            for (int i = 0; i < 4; i++) {
                int idx = tid + i * 128;
                int n = idx >> 2, kq = idx & 3;
                int cs = n ^ (kq << 3);
                Bsb[kq * 4 + 0][cs] = pb[i].x;
                Bsb[kq * 4 + 1][cs] = pb[i].y;
                Bsb[kq * 4 + 2][cs] = pb[i].z;
                Bsb[kq * 4 + 3][cs] = pb[i].w;
            }
        }
    };

    // Two K=16 slices per tile; compile-time buffer => [R+imm] addressing.
    auto compute = [&](const uint32_t (*Asb)[BM + PAD],
                       const uint32_t (*Bsb)[BN + PAD]) {
#pragma unroll
        for (int s = 0; s < 2; s++) {
            const int kpA = 8 * s + cg, kpB = 8 * s + cg + 4;
            const int c0 = 16 * s, c1 = 16 * s + 8;
            uint32_t afr[4][4], bfr[8][2];
#pragma unroll
            for (int mt = 0; mt < 4; mt++) {
                int mrow = m0 + mt * 16;
                afr[mt][0] = Asb[kpA][(mrow + r)     ^ c0];
                afr[mt][1] = Asb[kpA][(mrow + r + 8) ^ c0];
                afr[mt][2] = Asb[kpB][(mrow + r)     ^ c1];
                afr[mt][3] = Asb[kpB][(mrow + r + 8) ^ c1];
            }
#pragma unroll
            for (int nt = 0; nt < 8; nt++) {
                int ncol = n0 + nt * 8 + r;
                bfr[nt][0] = Bsb[kpA][ncol ^ c0];
                bfr[nt][1] = Bsb[kpB][ncol ^ c1];
            }
#pragma unroll
            for (int mt = 0; mt < 4; mt++)
#pragma unroll
                for (int nt = 0; nt < 8; nt++) mma16(acc[mt][nt], afr[mt], bfr[nt]);
        }
    };

    const int nk = Kl / BK;   // 16 or 32: always even
    loadA(koff); loadB(koff);
    storeA(As[0]); storeB(Bs[0]);
    __syncthreads();

    for (int kt = 0; kt < nk; kt += 2) {
        loadA(koff + (kt + 1) * BK); loadB(koff + (kt + 1) * BK);
        compute(As[0], Bs[0]);
        storeA(As[1]); storeB(Bs[1]);
        __syncthreads();
        const bool more = (kt + 2 < nk);
        if (more) { loadA(koff + (kt + 2) * BK); loadB(koff + (kt + 2) * BK); }
        compute(As[1], Bs[1]);
        if (more) {
            storeA(As[0]); storeB(Bs[0]);
            __syncthreads();
        }
    }

    // epilogue
    float* Df  = (float*)Dbase + (long)batch * sD + (long)sp * sSplit;
    __half* Dh = (__half*)Dbase + (long)batch * sD;
#pragma unroll
    for (int mt = 0; mt < 4; mt++) {
        int row0 = bm + m0 + mt * 16 + r;
#pragma unroll
        for (int nt = 0; nt < 8; nt++) {
            int col = bn + n0 + nt * 8 + cg * 2;
            float v0 = acc[mt][nt][0] * scale;
            float v1 = acc[mt][nt][1] * scale;
            float v2 = acc[mt][nt][2] * scale;
            float v3 = acc[mt][nt][3] * scale;
            if (biasMode == 1) {
                float b0 = bias[row0] * biasScale;
                float b1 = bias[row0 + 8] * biasScale;
                v0 += b0; v1 += b0; v2 += b1; v3 += b1;
            } else if (biasMode == 2) {
                float b0 = bias[col] * biasScale;
                float b1 = bias[col + 1] * biasScale;
                v0 += b0; v1 += b1; v2 += b0; v3 += b1;
            }
            if (OUT16) {
                *reinterpret_cast<uint32_t*>(&Dh[(long)row0 * N + col])       = pack2(v0, v1);
                *reinterpret_cast<uint32_t*>(&Dh[(long)(row0 + 8) * N + col]) = pack2(v2, v3);
            } else {
                Df[(long)row0 * N + col]           = v0;
                Df[(long)row0 * N + col + 1]       = v1;
                Df[(long)(row0 + 8) * N + col]     = v2;
                Df[(long)(row0 + 8) * N + col + 1] = v3;
            }
        }
    }
}

// f32 -> fp16 conversion, 8 elements/thread. n must be a multiple of 8.
__global__ __launch_bounds__(256, 8) void cvt_f2h(
    const float* __restrict__ in, __half* __restrict__ out, long n) {
    long i = ((long)blockIdx.x * 256 + threadIdx.x) * 8;
    if (i >= n) return;
    float4 a = *reinterpret_cast<const float4*>(in + i);
    float4 b = *reinterpret_cast<const float4*>(in + i + 4);
    uint4 o = make_uint4(pack2(a.x, a.y), pack2(a.z, a.w),
                         pack2(b.x, b.y), pack2(b.z, b.w));
    *reinterpret_cast<uint4*>(out + i) = o;
}

// In-place softmax over fp16 rows of length 4096 (f32 math). 256 thr/row.
__global__ __launch_bounds__(256, 1) void softmax_h(__half* __restrict__ buf) {
    __half* p = buf + (long)blockIdx.x * HW_;
    const int tid  = threadIdx.x;
    const int lane = tid & 31;
    const int warp = tid >> 5;
    __shared__ float red[8];

    uint4* p4 = reinterpret_cast<uint4*>(p);   // 512 uint4 per row
    uint4 u[2];
    float f[16];
#pragma unroll
    for (int i = 0; i < 2; i++) {
        u[i] = p4[i * 256 + tid];
        const uint32_t* w = &u[i].x;
#pragma unroll
        for (int j = 0; j < 4; j++) {
            float2 v = __half22float2(*reinterpret_cast<const __half2*>(&w[j]));
            f[i * 8 + j * 2]     = v.x;
            f[i * 8 + j * 2 + 1] = v.y;
        }
    }

    float mx = f[0];
#pragma unroll
    for (int i = 1; i < 16; i++) mx = fmaxf(mx, f[i]);
#pragma unroll
    for (int o = 16; o; o >>= 1) mx = fmaxf(mx, __shfl_xor_sync(0xffffffffu, mx, o));
    if (lane == 0) red[warp] = mx;
    __syncthreads();
    mx = red[0];
#pragma unroll
    for (int w = 1; w < 8; w++) mx = fmaxf(mx, red[w]);
    __syncthreads();

    float s = 0.f;
#pragma unroll
    for (int i = 0; i < 16; i++) { f[i] = __expf(f[i] - mx); s += f[i]; }
#pragma unroll
    for (int o = 16; o; o >>= 1) s += __shfl_xor_sync(0xffffffffu, s, o);
    if (lane == 0) red[warp] = s;
    __syncthreads();
    s = 0.f;
#pragma unroll
    for (int w = 0; w < 8; w++) s += red[w];
    const float inv = 1.f / s;
#pragma unroll
    for (int i = 0; i < 2; i++) {
        uint32_t* w = &u[i].x;
#pragma unroll
        for (int j = 0; j < 4; j++)
            w[j] = pack2(f[i * 8 + j * 2] * inv, f[i * 8 + j * 2 + 1] * inv);
        p4[i * 256 + tid] = u[i];
    }
}

// S16 = fp16((p0+p1+p2+p3) * scale)   (deterministic split-K reduction)
__global__ __launch_bounds__(256, 8) void reduceS(
    const float* __restrict__ p, __half* __restrict__ o, float scale) {
    const long NT = (long)BB * CC * CC / 4;  // float4 units per partial
    long i = (long)blockIdx.x * 256 + threadIdx.x;
    if (i >= NT) return;
    const float4* p4 = reinterpret_cast<const float4*>(p);
    float4 a = p4[i], b = p4[i + NT], c = p4[i + 2 * NT], d = p4[i + 3 * NT];
    float rx = (a.x + b.x + c.x + d.x) * scale;
    float ry = (a.y + b.y + c.y + d.y) * scale;
    float rz = (a.z + b.z + c.z + d.z) * scale;
    float rw = (a.w + b.w + c.w + d.w) * scale;
    uint2 w = make_uint2(pack2(rx, ry), pack2(rz, rw));
    reinterpret_cast<uint2*>(o)[i] = w;
}

extern "C" void kernel_launch(void* const* d_in, const int* in_sizes, int n_in,
                              void* d_out, int out_size) {
    const float* x  = (const float*)d_in[0];
    const float* wA = (const float*)d_in[1];
    const float* bA = (const float*)d_in[2];
    const float* wB = (const float*)d_in[3];
    const float* bB = (const float*)d_in[4];
    const float* wV = (const float*)d_in[5];
    const float* bV = (const float*)d_in[6];
    float* out = (float*)d_out;

    __half *xh, *wh, *logits, *S, *gd;
    float *Sp;
    cudaGetSymbolAddress((void**)&xh, g_xh);
    cudaGetSymbolAddress((void**)&wh, g_wh);
    cudaGetSymbolAddress((void**)&logits, g_logits16);
    cudaGetSymbolAddress((void**)&Sp, g_Sp);
    cudaGetSymbolAddress((void**)&S, g_S16);
    cudaGetSymbolAddress((void**)&gd, g_gd16);

    const long sX  = (long)CC * HW_;        // xh batch stride
    const long sL  = (long)2 * CC * HW_;    // logits batch stride
    const long sCC = (long)CC * CC;
    const long sSp = (long)BB * CC * CC;    // split-partial stride
    const float invHW = 1.0f / (float)HW_;
    dim3 blk(128);
    dim3 blk256(256);

    // 0) convert x and weights to fp16
    const long nX = (long)BB * CC * HW_;
    cvt_f2h<<<(unsigned)(nX / (256 * 8)), blk256>>>(x, xh, nX);
    cvt_f2h<<<(unsigned)(sCC / (256 * 8)), blk256>>>(wB, wh, sCC);
    cvt_f2h<<<(unsigned)(sCC / (256 * 8)), blk256>>>(wV, wh + sCC, sCC);
    cvt_f2h<<<(unsigned)(sCC / (256 * 8)), blk256>>>(wA, wh + 2 * sCC, sCC);

    // 1) B logits -> logits[b, 0:512, :] fp16   (B = xh as [K,N])
    gemm_h<false, 1, true><<<dim3(HW_ / BN, CC / BM, BB), blk>>>(
        wh, xh, logits, HW_, CC, 0, sX, sL, 0, bB, 1, 1.f, 1.f);
    // 2) V logits -> logits[b, 512:1024, :]
    gemm_h<false, 1, true><<<dim3(HW_ / BN, CC / BM, BB), blk>>>(
        wh + sCC, xh, logits + (long)CC * HW_, HW_, CC, 0, sX, sL, 0, bV, 1, 1.f, 1.f);
    // 3) softmax over all 8*1024 fp16 rows, in place
    softmax_h<<<BB * 2 * CC, blk256>>>(logits);
    // 4) S partials = Bm @ xh^T, split-K=4, f32 partials  (B = xh as [N,K])
    gemm_h<true, NSPLIT4, false><<<dim3(CC / BN, CC / BM, BB * NSPLIT4), blk>>>(
        logits, xh, Sp, CC, HW_, sL, sX, sCC, sSp, nullptr, 0, 1.f, 1.f);
    //    reduce partials -> S16 UNSCALED (keeps step-5/6 inputs O(1))
    reduceS<<<(unsigned)((sSp / 4 + 255) / 256), blk256>>>(Sp, S, 1.f);
    // 5) gdT = wAh @ S^T + bA -> fp16  (gd TRANSPOSED; B = S is [N,K])
    gemm_h<true, 1, true><<<dim3(CC / BN, CC / BM, BB), blk>>>(
        wh + 2 * sCC, S, gd, CC, CC, 0, sCC, sCC, 0, bA, 1, 1.f, 1.f);
    // 6) out = (gdT @ av) * 1/HW -> f32  (A = gdT row-major; B = av is [K,N])
    gemm_h<false, 1, false><<<dim3(HW_ / BN, CC / BM, BB), blk>>>(
        gd, logits + (long)CC * HW_, out, HW_, CC, sCC, sL, (long)CC * HW_, 0,
        nullptr, 0, invHW, 1.f);
}

// round 16
// speedup vs baseline: 1.4218x; 1.4218x over previous
#include <cuda_runtime.h>
#include <cuda_fp16.h>
#include <cstdint>

// ---------------------------------------------------------------------------
// DoubleAttention, all-fp16 operands, uniform K-contiguous GEMMs:
//   xh=[c][hw], xhT=[hw][c] = fp16(x)        (one fused pre-pass)
//   L_B = wBh @ xhT' ; L_V = wVh @ xhT'      (TB GEMMs, fp16 out [c][hw])
//   Bm, av = softmax_rows ; avT = av^T       (tiled transpose)
//   S = Bm @ xh' (split-K=4, f32 partials) -> S16 (unnormalized)
//   gdT = wAh @ S16' + bA                    (fp16 out)
//   out = (gdT @ avT') * 1/HW                (f32 out)
// GEMM core: m16n8k16 fp16 mma + f32 accum, BK=32, cp.async 3-stage pipeline
// (no prefetch registers), ldmatrix.x4 fragment loads (6 LDSM per 16 mma),
// 256 threads = 8 warps of 64x32, 2 CTAs/SM (16 warps). SMEM rows 64B with
// chunk^((row>>1)&3) swizzle: LDSM and cp.async stores conflict-free/phase.
// ---------------------------------------------------------------------------

#define BB   8
#define CC   512
#define HW_  4096
#define BM   128
#define BN   128
#define BK   32
#define NST  3
#define NSPLIT4 4

__device__ __align__(256) __half g_xh [BB * CC * HW_];       // 33.5MB
__device__ __align__(256) __half g_xhT[BB * CC * HW_];       // 33.5MB
__device__ __align__(256) __half g_wh [3 * CC * CC];         // wB|wV|wA
__device__ __align__(256) __half g_logits16[BB * 2 * CC * HW_]; // 67MB
__device__ __align__(256) __half g_avT[BB * CC * HW_];       // 33.5MB
__device__ __align__(256) float  g_Sp[NSPLIT4 * BB * CC * CC];  // 33.5MB
__device__ __align__(256) __half g_S16[BB * CC * CC];        // 4MB
__device__ __align__(256) __half g_gd16[BB * CC * CC];       // 4MB

__device__ __forceinline__ uint32_t pack2(float e, float o) {
    uint32_t u;
    asm("cvt.rn.f16x2.f32 %0, %1, %2;" : "=r"(u) : "f"(o), "f"(e));
    return u;
}
__device__ __forceinline__ void mma16(float* c, const uint32_t* a, const uint32_t* b) {
    asm volatile(
        "mma.sync.aligned.m16n8k16.row.col.f32.f16.f16.f32 "
        "{%0,%1,%2,%3},{%4,%5,%6,%7},{%8,%9},{%0,%1,%2,%3};"
        : "+f"(c[0]), "+f"(c[1]), "+f"(c[2]), "+f"(c[3])
        : "r"(a[0]), "r"(a[1]), "r"(a[2]), "r"(a[3]), "r"(b[0]), "r"(b[1]));
}
__device__ __forceinline__ void ldsm4(uint32_t* r, uint32_t a) {
    asm volatile("ldmatrix.sync.aligned.m8n8.x4.shared.b16 {%0,%1,%2,%3}, [%4];"
                 : "=r"(r[0]), "=r"(r[1]), "=r"(r[2]), "=r"(r[3]) : "r"(a));
}
__device__ __forceinline__ uint32_t s2u(const void* p) {
    uint32_t a;
    asm("{ .reg .u64 t; cvta.to.shared.u64 t, %1; cvt.u32.u64 %0, t; }" : "=r"(a) : "l"(p));
    return a;
}
__device__ __forceinline__ void cpa(uint32_t dst, const __half* src) {
    asm volatile("cp.async.ca.shared.global [%0], [%1], 16;"
                 :: "r"(dst), "l"(__cvta_generic_to_global(src)) : "memory");
}
#define CP_COMMIT() asm volatile("cp.async.commit_group;" ::: "memory")
#define CP_WAIT2()  asm volatile("cp.async.wait_group 2;" ::: "memory")

// D[m,n] = scale * sum_k A[m,k]*B[n,k]  (+ bias[row] if biasMode==1)
// A, B both fp16 [rows][K] row-major, K mult of 32, 16B-aligned rows.
template <int NSPLIT, bool OUT16>
__global__ __launch_bounds__(256, 2) void gemm_cp(
    const __half* __restrict__ Abase, const __half* __restrict__ Bbase,
    void* __restrict__ Dbase, int N, int K,
    long sA, long sB, long sD, long sSplit,
    const float* __restrict__ bias, int biasMode, float scale)
{
    __shared__ __align__(1024) uint8_t smA[NST][BM * BK * 2];  // 3x8KB
    __shared__ __align__(1024) uint8_t smB[NST][BN * BK * 2];  // 3x8KB

    const int bz    = blockIdx.z;
    const int batch = bz / NSPLIT;
    const int sp    = bz % NSPLIT;
    const int Kl    = K / NSPLIT;
    const int koff  = sp * Kl;

    const __half* A  = Abase + (long)batch * sA;
    const __half* Bq = Bbase + (long)batch * sB;

    const int bm   = blockIdx.y * BM;
    const int bn   = blockIdx.x * BN;
    const int tid  = threadIdx.x;
    const int lane = tid & 31;
    const int warp = tid >> 5;
    const int m0   = (warp & 1) * 64;   // 2 warps along M
    const int n0w  = (warp >> 1) * 32;  // 4 warps along N
    const int r    = lane >> 2;
    const int cg   = lane & 3;

    uint32_t aSm[NST], bSm[NST];
#pragma unroll
    for (int s = 0; s < NST; s++) { aSm[s] = s2u(smA[s]); bSm[s] = s2u(smB[s]); }

    // per-lane ldmatrix row roles
    const int mA  = m0 + (lane & 15);          // A rows (x4: lanes 0-15 klow)
    const int hiA = lane >> 4;                 // k-chunk select
    const int nB  = n0w + (lane & 7) + ((lane >> 4) << 3);  // B rows
    const int hiB = (lane >> 3) & 1;
    int aOff[4], xA[4], bOff[2], xB[2];
#pragma unroll
    for (int mt = 0; mt < 4; mt++) {
        int mr = mA + 16 * mt;
        aOff[mt] = mr * 64; xA[mt] = (mr >> 1) & 3;
    }
#pragma unroll
    for (int p = 0; p < 2; p++) {
        int nr = nB + 16 * p;
        bOff[p] = nr * 64; xB[p] = (nr >> 1) & 3;
    }

    float acc[4][4][4];
#pragma unroll
    for (int i = 0; i < 4; i++)
#pragma unroll
        for (int j = 0; j < 4; j++)
#pragma unroll
            for (int k = 0; k < 4; k++) acc[i][j][k] = 0.f;

    // cp.async one tile (A 128x32, B 128x32 halfs) into slot st
    auto issue = [&](int kt) {
        const int st = kt % NST;
        const int k0 = koff + kt * BK;
        const __half* Ap = A + (long)bm * K + k0;
        const __half* Bp = Bq + (long)bn * K + k0;
#pragma unroll
        for (int i = 0; i < 2; i++) {
            int u = tid + i * 256;              // 512 chunks of 16B per tile
            int row = u >> 2, c = u & 3;
            uint32_t off = row * 64 + ((c ^ ((row >> 1) & 3)) << 4);
            cpa(aSm[st] + off, Ap + (long)row * K + c * 8);
            cpa(bSm[st] + off, Bp + (long)row * K + c * 8);
        }
    };

    auto compute = [&](uint32_t aB, uint32_t bB) {
#pragma unroll
        for (int s = 0; s < 2; s++) {           // two K=16 slices
            uint32_t afr[4][4], bfr[2][4];
#pragma unroll
            for (int mt = 0; mt < 4; mt++)
                ldsm4(afr[mt], aB + aOff[mt] + (((2 * s + hiA) ^ xA[mt]) << 4));
#pragma unroll
            for (int p = 0; p < 2; p++)
                ldsm4(bfr[p], bB + bOff[p] + (((2 * s + hiB) ^ xB[p]) << 4));
#pragma unroll
            for (int mt = 0; mt < 4; mt++)
#pragma unroll
                for (int p = 0; p < 2; p++) {
                    mma16(acc[mt][2 * p],     afr[mt], &bfr[p][0]);
                    mma16(acc[mt][2 * p + 1], afr[mt], &bfr[p][2]);
                }
        }
    };

    const int nk = Kl / BK;                     // >= 16 for all steps
    issue(0); CP_COMMIT();
    issue(1); CP_COMMIT();
    issue(2); CP_COMMIT();

    for (int kt = 0; kt < nk; kt++) {
        CP_WAIT2();
        __syncthreads();
        const int st = kt % NST;
        compute(aSm[st], bSm[st]);
        __syncthreads();
        if (kt + NST < nk) issue(kt + NST);
        CP_COMMIT();                            // empty groups keep counts aligned
    }

    // epilogue: direct stores from accumulators
    float*  Df = (float*)Dbase  + (long)batch * sD + (long)sp * sSplit;
    __half* Dh = (__half*)Dbase + (long)batch * sD;
#pragma unroll
    for (int mt = 0; mt < 4; mt++) {
        int row0 = bm + m0 + mt * 16 + r;
#pragma unroll
        for (int nt = 0; nt < 4; nt++) {
            int col = bn + n0w + nt * 8 + cg * 2;
            float v0 = acc[mt][nt][0] * scale;
            float v1 = acc[mt][nt][1] * scale;
            float v2 = acc[mt][nt][2] * scale;
            float v3 = acc[mt][nt][3] * scale;
            if (biasMode == 1) {
                float b0 = bias[row0], b1 = bias[row0 + 8];
                v0 += b0; v1 += b0; v2 += b1; v3 += b1;
            }
            if (OUT16) {
                *reinterpret_cast<uint32_t*>(&Dh[(long)row0 * N + col])       = pack2(v0, v1);
                *reinterpret_cast<uint32_t*>(&Dh[(long)(row0 + 8) * N + col]) = pack2(v2, v3);
            } else {
                Df[(long)row0 * N + col]           = v0;
                Df[(long)row0 * N + col + 1]       = v1;
                Df[(long)(row0 + 8) * N + col]     = v2;
                Df[(long)(row0 + 8) * N + col + 1] = v3;
            }
        }
    }
}

// fused: xh = fp16(x) (same layout) and xhT = fp16(x)^T, 64x64 tiles
__global__ __launch_bounds__(256, 4) void cvt_x(
    const float* __restrict__ x, __half* __restrict__ xh, __half* __restrict__ xhT)
{
    __shared__ __half t[64][65];
    const long b = blockIdx.z;
    const int c0 = blockIdx.y * 64, h0 = blockIdx.x * 64;
    const float* ip = x  + (b * CC + c0) * (long)HW_ + h0;
    __half* hp = xh  + (b * CC + c0) * (long)HW_ + h0;
    __half* tp = xhT + b * (long)CC * HW_ + (long)h0 * CC + c0;
    const int rr = threadIdx.x >> 4, q = (threadIdx.x & 15) * 4;
#pragma unroll
    for (int i = 0; i < 4; i++) {
        int row = rr + i * 16;
        float4 v = *reinterpret_cast<const float4*>(ip + (long)row * HW_ + q);
        uint2 o = make_uint2(pack2(v.x, v.y), pack2(v.z, v.w));
        *reinterpret_cast<uint2*>(hp + (long)row * HW_ + q) = o;
        t[row][q]     = __float2half_rn(v.x);
        t[row][q + 1] = __float2half_rn(v.y);
        t[row][q + 2] = __float2half_rn(v.z);
        t[row][q + 3] = __float2half_rn(v.w);
    }
    __syncthreads();
    const int r2 = threadIdx.x >> 5, c2 = (threadIdx.x & 31) * 2;
#pragma unroll
    for (int i = 0; i < 8; i++) {
        int hw = r2 + i * 8;
        __half2 v; v.x = t[c2][hw]; v.y = t[c2 + 1][hw];
        *reinterpret_cast<__half2*>(tp + (long)hw * CC + c2) = v;
    }
}

// fp16 [c][hw] -> [hw][c] transpose (for av)
__global__ __launch_bounds__(256, 4) void transpose_h(
    const __half* __restrict__ in, __half* __restrict__ out, long sIn, long sOut)
{
    __shared__ __half t[64][65];
    const long b = blockIdx.z;
    const int c0 = blockIdx.y * 64, h0 = blockIdx.x * 64;
    const __half* ip = in + b * sIn + (long)c0 * HW_ + h0;
    __half* op = out + b * sOut + (long)h0 * CC + c0;
    const int rr = threadIdx.x >> 4, q = (threadIdx.x & 15) * 4;
#pragma unroll
    for (int i = 0; i < 4; i++) {
        int row = rr + i * 16;
        uint2 v = *reinterpret_cast<const uint2*>(ip + (long)row * HW_ + q);
        __half2 a = *reinterpret_cast<__half2*>(&v.x);
        __half2 c = *reinterpret_cast<__half2*>(&v.y);
        t[row][q] = a.x; t[row][q + 1] = a.y; t[row][q + 2] = c.x; t[row][q + 3] = c.y;
    }
    __syncthreads();
    const int r2 = threadIdx.x >> 5, c2 = (threadIdx.x & 31) * 2;
#pragma unroll
    for (int i = 0; i < 8; i++) {
        int hw = r2 + i * 8;
        __half2 v; v.x = t[c2][hw]; v.y = t[c2 + 1][hw];
        *reinterpret_cast<__half2*>(op + (long)hw * CC + c2) = v;
    }
}

// f32 -> fp16, 8 elems/thread
__global__ __launch_bounds__(256, 8) void cvt_f2h(
    const float* __restrict__ in, __half* __restrict__ out, long n) {
    long i = ((long)blockIdx.x * 256 + threadIdx.x) * 8;
    if (i >= n) return;
    float4 a = *reinterpret_cast<const float4*>(in + i);
    float4 b = *reinterpret_cast<const float4*>(in + i + 4);
    uint4 o = make_uint4(pack2(a.x, a.y), pack2(a.z, a.w),
                         pack2(b.x, b.y), pack2(b.z, b.w));
    *reinterpret_cast<uint4*>(out + i) = o;
}

// in-place softmax over fp16 rows of 4096 (f32 math)
__global__ __launch_bounds__(256, 1) void softmax_h(__half* __restrict__ buf) {
    __half* p = buf + (long)blockIdx.x * HW_;
    const int tid = threadIdx.x, lane = tid & 31, warp = tid >> 5;
    __shared__ float red[8];
    uint4* p4 = reinterpret_cast<uint4*>(p);
    uint4 u[2];
    float f[16];
#pragma unroll
    for (int i = 0; i < 2; i++) {
        u[i] = p4[i * 256 + tid];
        const uint32_t* w = &u[i].x;
#pragma unroll
        for (int j = 0; j < 4; j++) {
            float2 v = __half22float2(*reinterpret_cast<const __half2*>(&w[j]));
            f[i * 8 + j * 2] = v.x; f[i * 8 + j * 2 + 1] = v.y;
        }
    }
    float mx = f[0];
#pragma unroll
    for (int i = 1; i < 16; i++) mx = fmaxf(mx, f[i]);
#pragma unroll
    for (int o = 16; o; o >>= 1) mx = fmaxf(mx, __shfl_xor_sync(0xffffffffu, mx, o));
    if (lane == 0) red[warp] = mx;
    __syncthreads();
    mx = red[0];
#pragma unroll
    for (int w = 1; w < 8; w++) mx = fmaxf(mx, red[w]);
    __syncthreads();
    float s = 0.f;
#pragma unroll
    for (int i = 0; i < 16; i++) { f[i] = __expf(f[i] - mx); s += f[i]; }
#pragma unroll
    for (int o = 16; o; o >>= 1) s += __shfl_xor_sync(0xffffffffu, s, o);
    if (lane == 0) red[warp] = s;
    __syncthreads();
    s = 0.f;
#pragma unroll
    for (int w = 0; w < 8; w++) s += red[w];
    const float inv = 1.f / s;
#pragma unroll
    for (int i = 0; i < 2; i++) {
        uint32_t* w = &u[i].x;
#pragma unroll
        for (int j = 0; j < 4; j++)
            w[j] = pack2(f[i * 8 + j * 2] * inv, f[i * 8 + j * 2 + 1] * inv);
        p4[i * 256 + tid] = u[i];
    }
}

// S16 = fp16(p0+p1+p2+p3)  (deterministic split-K reduction, unscaled)
__global__ __launch_bounds__(256, 8) void reduceS(
    const float* __restrict__ p, __half* __restrict__ o) {
    const long NT = (long)BB * CC * CC / 4;
    long i = (long)blockIdx.x * 256 + threadIdx.x;
    if (i >= NT) return;
    const float4* p4 = reinterpret_cast<const float4*>(p);
    float4 a = p4[i], b = p4[i + NT], c = p4[i + 2 * NT], d = p4[i + 3 * NT];
    uint2 w = make_uint2(pack2(a.x + b.x + c.x + d.x, a.y + b.y + c.y + d.y),
                         pack2(a.z + b.z + c.z + d.z, a.w + b.w + c.w + d.w));
    reinterpret_cast<uint2*>(o)[i] = w;
}

extern "C" void kernel_launch(void* const* d_in, const int* in_sizes, int n_in,
                              void* d_out, int out_size) {
    const float* x  = (const float*)d_in[0];
    const float* wA = (const float*)d_in[1];
    const float* bA = (const float*)d_in[2];
    const float* wB = (const float*)d_in[3];
    const float* bB = (const float*)d_in[4];
    const float* wV = (const float*)d_in[5];
    const float* bV = (const float*)d_in[6];
    float* out = (float*)d_out;

    __half *xh, *xhT, *wh, *logits, *avT, *S, *gd;
    float* Sp;
    cudaGetSymbolAddress((void**)&xh, g_xh);
    cudaGetSymbolAddress((void**)&xhT, g_xhT);
    cudaGetSymbolAddress((void**)&wh, g_wh);
    cudaGetSymbolAddress((void**)&logits, g_logits16);
    cudaGetSymbolAddress((void**)&avT, g_avT);
    cudaGetSymbolAddress((void**)&Sp, g_Sp);
    cudaGetSymbolAddress((void**)&S, g_S16);
    cudaGetSymbolAddress((void**)&gd, g_gd16);

    const long sX  = (long)CC * HW_;
    const long sL  = (long)2 * CC * HW_;
    const long sCC = (long)CC * CC;
    const long sSp = (long)BB * CC * CC;
    const float invHW = 1.0f / (float)HW_;
    dim3 b256(256);

    // 0) fp16 conversions: xh + xhT fused; weights
    cvt_x<<<dim3(HW_ / 64, CC / 64, BB), b256>>>(x, xh, xhT);
    cvt_f2h<<<(unsigned)(sCC / (256 * 8)), b256>>>(wB, wh, sCC);
    cvt_f2h<<<(unsigned)(sCC / (256 * 8)), b256>>>(wV, wh + sCC, sCC);
    cvt_f2h<<<(unsigned)(sCC / (256 * 8)), b256>>>(wA, wh + 2 * sCC, sCC);

    // 1) B logits = wBh @ x : A=wBh [512,512], B=xhT [hw][c] -> fp16 [c][hw]
    gemm_cp<1, true><<<dim3(HW_ / BN, CC / BM, BB), b256>>>(
        wh, xhT, logits, HW_, CC, 0, sX, sL, 0, bB, 1, 1.f);
    // 2) V logits
    gemm_cp<1, true><<<dim3(HW_ / BN, CC / BM, BB), b256>>>(
        wh + sCC, xhT, logits + (long)CC * HW_, HW_, CC, 0, sX, sL, 0, bV, 1, 1.f);
    // 3) softmax (both halves, in place)
    softmax_h<<<BB * 2 * CC, b256>>>(logits);
    // 3b) avT = av^T
    transpose_h<<<dim3(HW_ / 64, CC / 64, BB), b256>>>(
        logits + (long)CC * HW_, avT, sL, (long)CC * HW_);
    // 4) S partials = Bm @ xh^T : A=Bm [c][hw], B=xh [c][hw], split-K=4
    gemm_cp<NSPLIT4, false><<<dim3(CC / BN, CC / BM, BB * NSPLIT4), b256>>>(
        logits, xh, Sp, CC, HW_, sL, sX, sCC, sSp, nullptr, 0, 1.f);
    reduceS<<<(unsigned)((sSp / 4 + 255) / 256), b256>>>(Sp, S);
    // 5) gdT = wAh @ S^T + bA : A=wAh, B=S16 [i][c]
    gemm_cp<1, true><<<dim3(CC / BN, CC / BM, BB), b256>>>(
        wh + 2 * sCC, S, gd, CC, CC, 0, sCC, sCC, 0, bA, 1, 1.f);
    // 6) out = (gdT @ av) * 1/HW : A=gdT [j][i], B=avT [hw][i] -> f32 [c][hw]
    gemm_cp<1, false><<<dim3(HW_ / BN, CC / BM, BB), b256>>>(
        gd, avT, out, HW_, CC, sCC, (long)CC * HW_, (long)CC * HW_, 0,
        nullptr, 0, invHW);
}

// round 17
// speedup vs baseline: 1.5876x; 1.1167x over previous
#include <cuda_runtime.h>
#include <cuda_fp16.h>
#include <cstdint>

// ---------------------------------------------------------------------------
// DoubleAttention, all-fp16 operands, uniform K-contiguous GEMMs:
//   xh=[c][hw], xhT=[hw][c] = fp16(x)        (one fused pre-pass)
//   L = [wBh;wVh] @ xhT'                     (ONE fused GEMM M=1024, fp16 out)
//   Bm, av = softmax_rows ; avT = av^T       (tiled transpose)
//   S = Bm @ xh' (split-K=4, f32 partials) -> S16 (unnormalized)
//   gdT = wAh @ S16' + bA                    (fp16 out)
//   out = (gdT @ avT') * 1/HW                (f32 out)
// GEMM core: m16n8k16 fp16 mma + f32 accum, BK=32, cp.async 3-stage pipeline
// with a SINGLE __syncthreads per k-tile (CUTLASS multistage order: the
// top-of-iter sync orders issue(kt+2) into slot (kt-1)%3 after all warps
// finished compute(kt-1)). ldmatrix.x4 fragment loads, 8 warps of 64x32,
// 2 CTAs/SM. SMEM rows 64B, chunk^((row>>1)&3) swizzle (conflict-free).
// ---------------------------------------------------------------------------

#define BB   8
#define CC   512
#define HW_  4096
#define BM   128
#define BN   128
#define BK   32
#define NST  3
#define NSPLIT4 4

__device__ __align__(256) __half g_xh [BB * CC * HW_];       // 33.5MB
__device__ __align__(256) __half g_xhT[BB * CC * HW_];       // 33.5MB
__device__ __align__(256) __half g_wh [3 * CC * CC];         // wB|wV|wA
__device__ __align__(256) float  g_bcomb[2 * CC];            // bB|bV
__device__ __align__(256) __half g_logits16[BB * 2 * CC * HW_]; // 67MB
__device__ __align__(256) __half g_avT[BB * CC * HW_];       // 33.5MB
__device__ __align__(256) float  g_Sp[NSPLIT4 * BB * CC * CC];  // 33.5MB
__device__ __align__(256) __half g_S16[BB * CC * CC];        // 4MB
__device__ __align__(256) __half g_gd16[BB * CC * CC];       // 4MB

__device__ __forceinline__ uint32_t pack2(float e, float o) {
    uint32_t u;
    asm("cvt.rn.f16x2.f32 %0, %1, %2;" : "=r"(u) : "f"(o), "f"(e));
    return u;
}
__device__ __forceinline__ void mma16(float* c, const uint32_t* a, const uint32_t* b) {
    asm volatile(
        "mma.sync.aligned.m16n8k16.row.col.f32.f16.f16.f32 "
        "{%0,%1,%2,%3},{%4,%5,%6,%7},{%8,%9},{%0,%1,%2,%3};"
        : "+f"(c[0]), "+f"(c[1]), "+f"(c[2]), "+f"(c[3])
        : "r"(a[0]), "r"(a[1]), "r"(a[2]), "r"(a[3]), "r"(b[0]), "r"(b[1]));
}
__device__ __forceinline__ void ldsm4(uint32_t* r, uint32_t a) {
    asm volatile("ldmatrix.sync.aligned.m8n8.x4.shared.b16 {%0,%1,%2,%3}, [%4];"
                 : "=r"(r[0]), "=r"(r[1]), "=r"(r[2]), "=r"(r[3]) : "r"(a));
}
__device__ __forceinline__ uint32_t s2u(const void* p) {
    uint32_t a;
    asm("{ .reg .u64 t; cvta.to.shared.u64 t, %1; cvt.u32.u64 %0, t; }" : "=r"(a) : "l"(p));
    return a;
}
__device__ __forceinline__ void cpa(uint32_t dst, const __half* src) {
    asm volatile("cp.async.ca.shared.global [%0], [%1], 16;"
                 :: "r"(dst), "l"(__cvta_generic_to_global(src)) : "memory");
}
#define CP_COMMIT() asm volatile("cp.async.commit_group;" ::: "memory")
#define CP_WAIT1()  asm volatile("cp.async.wait_group 1;" ::: "memory")

// D[m,n] = scale * sum_k A[m,k]*B[n,k]  (+ bias[row] if biasMode==1)
// A, B both fp16 [rows][K] row-major, K mult of 32, 16B-aligned rows.
template <int NSPLIT, bool OUT16>
__global__ __launch_bounds__(256, 2) void gemm_cp(
    const __half* __restrict__ Abase, const __half* __restrict__ Bbase,
    void* __restrict__ Dbase, int N, int K,
    long sA, long sB, long sD, long sSplit,
    const float* __restrict__ bias, int biasMode, float scale)
{
    __shared__ __align__(1024) uint8_t smA[NST][BM * BK * 2];  // 3x8KB
    __shared__ __align__(1024) uint8_t smB[NST][BN * BK * 2];  // 3x8KB

    const int bz    = blockIdx.z;
    const int batch = bz / NSPLIT;
    const int sp    = bz % NSPLIT;
    const int Kl    = K / NSPLIT;
    const int koff  = sp * Kl;

    const __half* A  = Abase + (long)batch * sA;
    const __half* Bq = Bbase + (long)batch * sB;

    const int bm   = blockIdx.y * BM;
    const int bn   = blockIdx.x * BN;
    const int tid  = threadIdx.x;
    const int lane = tid & 31;
    const int warp = tid >> 5;
    const int m0   = (warp & 1) * 64;   // 2 warps along M
    const int n0w  = (warp >> 1) * 32;  // 4 warps along N
    const int r    = lane >> 2;
    const int cg   = lane & 3;

    uint32_t aSm[NST], bSm[NST];
#pragma unroll
    for (int s = 0; s < NST; s++) { aSm[s] = s2u(smA[s]); bSm[s] = s2u(smB[s]); }

    // per-lane ldmatrix row roles
    const int mA  = m0 + (lane & 15);
    const int hiA = lane >> 4;
    const int nB  = n0w + (lane & 7) + ((lane >> 4) << 3);
    const int hiB = (lane >> 3) & 1;
    int aOff[4], xA[4], bOff[2], xB[2];
#pragma unroll
    for (int mt = 0; mt < 4; mt++) {
        int mr = mA + 16 * mt;
        aOff[mt] = mr * 64; xA[mt] = (mr >> 1) & 3;
    }
#pragma unroll
    for (int p = 0; p < 2; p++) {
        int nr = nB + 16 * p;
        bOff[p] = nr * 64; xB[p] = (nr >> 1) & 3;
    }

    float acc[4][4][4];
#pragma unroll
    for (int i = 0; i < 4; i++)
#pragma unroll
        for (int j = 0; j < 4; j++)
#pragma unroll
            for (int k = 0; k < 4; k++) acc[i][j][k] = 0.f;

    auto issue = [&](int kt) {
        const int st = kt % NST;
        const int k0 = koff + kt * BK;
        const __half* Ap = A + (long)bm * K + k0;
        const __half* Bp = Bq + (long)bn * K + k0;
#pragma unroll
        for (int i = 0; i < 2; i++) {
            int u = tid + i * 256;
            int row = u >> 2, c = u & 3;
            uint32_t off = row * 64 + ((c ^ ((row >> 1) & 3)) << 4);
            cpa(aSm[st] + off, Ap + (long)row * K + c * 8);
            cpa(bSm[st] + off, Bp + (long)row * K + c * 8);
        }
    };

    auto compute = [&](uint32_t aB, uint32_t bB) {
#pragma unroll
        for (int s = 0; s < 2; s++) {
            uint32_t afr[4][4], bfr[2][4];
#pragma unroll
            for (int mt = 0; mt < 4; mt++)
                ldsm4(afr[mt], aB + aOff[mt] + (((2 * s + hiA) ^ xA[mt]) << 4));
#pragma unroll
            for (int p = 0; p < 2; p++)
                ldsm4(bfr[p], bB + bOff[p] + (((2 * s + hiB) ^ xB[p]) << 4));
#pragma unroll
            for (int mt = 0; mt < 4; mt++)
#pragma unroll
                for (int p = 0; p < 2; p++) {
                    mma16(acc[mt][2 * p],     afr[mt], &bfr[p][0]);
                    mma16(acc[mt][2 * p + 1], afr[mt], &bfr[p][2]);
                }
        }
    };

    const int nk = Kl / BK;                 // >= 16 everywhere
    issue(0); CP_COMMIT();
    issue(1); CP_COMMIT();

    for (int kt = 0; kt < nk; kt++) {
        CP_WAIT1();                         // group kt complete (2 in flight max)
        __syncthreads();                    // orders next issue after compute(kt-1)
        if (kt + 2 < nk) issue(kt + 2);     // slot (kt-1)%3: safe per sync above
        CP_COMMIT();
        const int st = kt % NST;
        compute(aSm[st], bSm[st]);
    }

    // epilogue
    float*  Df = (float*)Dbase  + (long)batch * sD + (long)sp * sSplit;
    __half* Dh = (__half*)Dbase + (long)batch * sD;
#pragma unroll
    for (int mt = 0; mt < 4; mt++) {
        int row0 = bm + m0 + mt * 16 + r;
#pragma unroll
        for (int nt = 0; nt < 4; nt++) {
            int col = bn + n0w + nt * 8 + cg * 2;
            float v0 = acc[mt][nt][0] * scale;
            float v1 = acc[mt][nt][1] * scale;
            float v2 = acc[mt][nt][2] * scale;
            float v3 = acc[mt][nt][3] * scale;
            if (biasMode == 1) {
                float b0 = bias[row0], b1 = bias[row0 + 8];
                v0 += b0; v1 += b0; v2 += b1; v3 += b1;
            }
            if (OUT16) {
                *reinterpret_cast<uint32_t*>(&Dh[(long)row0 * N + col])       = pack2(v0, v1);
                *reinterpret_cast<uint32_t*>(&Dh[(long)(row0 + 8) * N + col]) = pack2(v2, v3);
            } else {
                Df[(long)row0 * N + col]           = v0;
                Df[(long)row0 * N + col + 1]       = v1;
                Df[(long)(row0 + 8) * N + col]     = v2;
                Df[(long)(row0 + 8) * N + col + 1] = v3;
            }
        }
    }
}

// fused: xh = fp16(x) and xhT = fp16(x)^T, 64x64 tiles
__global__ __launch_bounds__(256, 4) void cvt_x(
    const float* __restrict__ x, __half* __restrict__ xh, __half* __restrict__ xhT)
{
    __shared__ __half t[64][65];
    const long b = blockIdx.z;
    const int c0 = blockIdx.y * 64, h0 = blockIdx.x * 64;
    const float* ip = x  + (b * CC + c0) * (long)HW_ + h0;
    __half* hp = xh  + (b * CC + c0) * (long)HW_ + h0;
    __half* tp = xhT + b * (long)CC * HW_ + (long)h0 * CC + c0;
    const int rr = threadIdx.x >> 4, q = (threadIdx.x & 15) * 4;
#pragma unroll
    for (int i = 0; i < 4; i++) {
        int row = rr + i * 16;
        float4 v = *reinterpret_cast<const float4*>(ip + (long)row * HW_ + q);
        uint2 o = make_uint2(pack2(v.x, v.y), pack2(v.z, v.w));
        *reinterpret_cast<uint2*>(hp + (long)row * HW_ + q) = o;
        t[row][q]     = __float2half_rn(v.x);
        t[row][q + 1] = __float2half_rn(v.y);
        t[row][q + 2] = __float2half_rn(v.z);
        t[row][q + 3] = __float2half_rn(v.w);
    }
    __syncthreads();
    const int r2 = threadIdx.x >> 5, c2 = (threadIdx.x & 31) * 2;
#pragma unroll
    for (int i = 0; i < 8; i++) {
        int hw = r2 + i * 8;
        __half2 v; v.x = t[c2][hw]; v.y = t[c2 + 1][hw];
        *reinterpret_cast<__half2*>(tp + (long)hw * CC + c2) = v;
    }
}

// fp16 [c][hw] -> [hw][c] transpose (for av)
__global__ __launch_bounds__(256, 4) void transpose_h(
    const __half* __restrict__ in, __half* __restrict__ out, long sIn, long sOut)
{
    __shared__ __half t[64][65];
    const long b = blockIdx.z;
    const int c0 = blockIdx.y * 64, h0 = blockIdx.x * 64;
    const __half* ip = in + b * sIn + (long)c0 * HW_ + h0;
    __half* op = out + b * sOut + (long)h0 * CC + c0;
    const int rr = threadIdx.x >> 4, q = (threadIdx.x & 15) * 4;
#pragma unroll
    for (int i = 0; i < 4; i++) {
        int row = rr + i * 16;
        uint2 v = *reinterpret_cast<const uint2*>(ip + (long)row * HW_ + q);
        __half2 a = *reinterpret_cast<__half2*>(&v.x);
        __half2 c = *reinterpret_cast<__half2*>(&v.y);
        t[row][q] = a.x; t[row][q + 1] = a.y; t[row][q + 2] = c.x; t[row][q + 3] = c.y;
    }
    __syncthreads();
    const int r2 = threadIdx.x >> 5, c2 = (threadIdx.x & 31) * 2;
#pragma unroll
    for (int i = 0; i < 8; i++) {
        int hw = r2 + i * 8;
        __half2 v; v.x = t[c2][hw]; v.y = t[c2 + 1][hw];
        *reinterpret_cast<__half2*>(op + (long)hw * CC + c2) = v;
    }
}

// fused weight conversion (wB|wV|wA -> fp16) + combined bias (bB|bV -> f32)
__global__ __launch_bounds__(256, 8) void cvt_w(
    const float* __restrict__ wB, const float* __restrict__ wV,
    const float* __restrict__ wA, const float* __restrict__ bB,
    const float* __restrict__ bV, __half* __restrict__ wh,
    float* __restrict__ bcomb)
{
    const long n1 = (long)CC * CC / 8;   // 8-elem units per weight
    long t = (long)blockIdx.x * 256 + threadIdx.x;
    if (t < 3 * n1) {
        int sel = (int)(t / n1);
        long u = t - sel * n1;
        const float* src = sel == 0 ? wB : (sel == 1 ? wV : wA);
        long i = u * 8;
        float4 a = *reinterpret_cast<const float4*>(src + i);
        float4 b = *reinterpret_cast<const float4*>(src + i + 4);
        uint4 o = make_uint4(pack2(a.x, a.y), pack2(a.z, a.w),
                             pack2(b.x, b.y), pack2(b.z, b.w));
        *reinterpret_cast<uint4*>(wh + sel * (long)CC * CC + i) = o;
    }
    if (t < 2 * CC) bcomb[t] = t < CC ? bB[t] : bV[t - CC];
}

// in-place softmax over fp16 rows of 4096 (f32 math)
__global__ __launch_bounds__(256, 1) void softmax_h(__half* __restrict__ buf) {
    __half* p = buf + (long)blockIdx.x * HW_;
    const int tid = threadIdx.x, lane = tid & 31, warp = tid >> 5;
    __shared__ float red[8];
    uint4* p4 = reinterpret_cast<uint4*>(p);
    uint4 u[2];
    float f[16];
#pragma unroll
    for (int i = 0; i < 2; i++) {
        u[i] = p4[i * 256 + tid];
        const uint32_t* w = &u[i].x;
#pragma unroll
        for (int j = 0; j < 4; j++) {
            float2 v = __half22float2(*reinterpret_cast<const __half2*>(&w[j]));
            f[i * 8 + j * 2] = v.x; f[i * 8 + j * 2 + 1] = v.y;
        }
    }
    float mx = f[0];
#pragma unroll
    for (int i = 1; i < 16; i++) mx = fmaxf(mx, f[i]);
#pragma unroll
    for (int o = 16; o; o >>= 1) mx = fmaxf(mx, __shfl_xor_sync(0xffffffffu, mx, o));
    if (lane == 0) red[warp] = mx;
    __syncthreads();
    mx = red[0];
#pragma unroll
    for (int w = 1; w < 8; w++) mx = fmaxf(mx, red[w]);
    __syncthreads();
    float s = 0.f;
#pragma unroll
    for (int i = 0; i < 16; i++) { f[i] = __expf(f[i] - mx); s += f[i]; }
#pragma unroll
    for (int o = 16; o; o >>= 1) s += __shfl_xor_sync(0xffffffffu, s, o);
    if (lane == 0) red[warp] = s;
    __syncthreads();
    s = 0.f;
#pragma unroll
    for (int w = 0; w < 8; w++) s += red[w];
    const float inv = 1.f / s;
#pragma unroll
    for (int i = 0; i < 2; i++) {
        uint32_t* w = &u[i].x;
#pragma unroll
        for (int j = 0; j < 4; j++)
            w[j] = pack2(f[i * 8 + j * 2] * inv, f[i * 8 + j * 2 + 1] * inv);
        p4[i * 256 + tid] = u[i];
    }
}

// S16 = fp16(p0+p1+p2+p3)  (deterministic split-K reduction, unscaled)
__global__ __launch_bounds__(256, 8) void reduceS(
    const float* __restrict__ p, __half* __restrict__ o) {
    const long NT = (long)BB * CC * CC / 4;
    long i = (long)blockIdx.x * 256 + threadIdx.x;
    if (i >= NT) return;
    const float4* p4 = reinterpret_cast<const float4*>(p);
    float4 a = p4[i], b = p4[i + NT], c = p4[i + 2 * NT], d = p4[i + 3 * NT];
    uint2 w = make_uint2(pack2(a.x + b.x + c.x + d.x, a.y + b.y + c.y + d.y),
                         pack2(a.z + b.z + c.z + d.z, a.w + b.w + c.w + d.w));
    reinterpret_cast<uint2*>(o)[i] = w;
}

extern "C" void kernel_launch(void* const* d_in, const int* in_sizes, int n_in,
                              void* d_out, int out_size) {
    const float* x  = (const float*)d_in[0];
    const float* wA = (const float*)d_in[1];
    const float* bA = (const float*)d_in[2];
    const float* wB = (const float*)d_in[3];
    const float* bB = (const float*)d_in[4];
    const float* wV = (const float*)d_in[5];
    const float* bV = (const float*)d_in[6];
    float* out = (float*)d_out;

    __half *xh, *xhT, *wh, *logits, *avT, *S, *gd;
    float *Sp, *bcomb;
    cudaGetSymbolAddress((void**)&xh, g_xh);
    cudaGetSymbolAddress((void**)&xhT, g_xhT);
    cudaGetSymbolAddress((void**)&wh, g_wh);
    cudaGetSymbolAddress((void**)&bcomb, g_bcomb);
    cudaGetSymbolAddress((void**)&logits, g_logits16);
    cudaGetSymbolAddress((void**)&avT, g_avT);
    cudaGetSymbolAddress((void**)&Sp, g_Sp);
    cudaGetSymbolAddress((void**)&S, g_S16);
    cudaGetSymbolAddress((void**)&gd, g_gd16);

    const long sX  = (long)CC * HW_;
    const long sL  = (long)2 * CC * HW_;
    const long sCC = (long)CC * CC;
    const long sSp = (long)BB * CC * CC;
    const float invHW = 1.0f / (float)HW_;
    dim3 b256(256);

    // 0) fp16 conversions: xh + xhT fused; all weights + combined bias fused
    cvt_x<<<dim3(HW_ / 64, CC / 64, BB), b256>>>(x, xh, xhT);
    cvt_w<<<(unsigned)((3 * sCC / 8 + 255) / 256), b256>>>(wB, wV, wA, bB, bV, wh, bcomb);

    // 1+2) L = [wBh;wVh] @ x : ONE GEMM, A=wh [1024,512], B=xhT [hw][c]
    gemm_cp<1, true><<<dim3(HW_ / BN, 2 * CC / BM, BB), b256>>>(
        wh, xhT, logits, HW_, CC, 0, sX, sL, 0, bcomb, 1, 1.f);
    // 3) softmax (both halves, in place)
    softmax_h<<<BB * 2 * CC, b256>>>(logits);
    // 3b) avT = av^T
    transpose_h<<<dim3(HW_ / 64, CC / 64, BB), b256>>>(
        logits + (long)CC * HW_, avT, sL, (long)CC * HW_);
    // 4) S partials = Bm @ xh^T : A=Bm [c][hw], B=xh [c][hw], split-K=4
    gemm_cp<NSPLIT4, false><<<dim3(CC / BN, CC / BM, BB * NSPLIT4), b256>>>(
        logits, xh, Sp, CC, HW_, sL, sX, sCC, sSp, nullptr, 0, 1.f);
    reduceS<<<(unsigned)((sSp / 4 + 255) / 256), b256>>>(Sp, S);
    // 5) gdT = wAh @ S^T + bA : A=wAh, B=S16 [i][c]
    gemm_cp<1, true><<<dim3(CC / BN, CC / BM, BB), b256>>>(
        wh + 2 * sCC, S, gd, CC, CC, 0, sCC, sCC, 0, bA, 1, 1.f);
    // 6) out = (gdT @ av) * 1/HW : A=gdT [j][i], B=avT [hw][i] -> f32 [c][hw]
    gemm_cp<1, false><<<dim3(HW_ / BN, CC / BM, BB), b256>>>(
        gd, avT, out, HW_, CC, sCC, (long)CC * HW_, (long)CC * HW_, 0,
        nullptr, 0, invHW);
}